// round 16
// baseline (speedup 1.0000x reference)
#include <cuda_runtime.h>
#include <stdint.h>
#include <math.h>

#define B_   2
#define S_   1024
#define D_   2048
#define NH   32
#define HDIM 64
#define ID_  8192
#define AH_  64
#define BS_  (B_*S_)

// ---------------- scratch (device globals; no runtime allocation) ----------
__device__ float g_h  [BS_*D_];
__device__ float g_q  [BS_*D_];
__device__ float g_k  [BS_*D_];
__device__ float g_v  [BS_*D_];
__device__ float g_attn[(size_t)B_*NH*S_*S_];   // 256 MB
__device__ float g_ao [BS_*D_];
__device__ float g_h1 [BS_*D_];
__device__ float g_h1t[BS_*D_];
__device__ float g_adj[(size_t)B_*S_*S_];
__device__ float g_msg[BS_*D_];
__device__ float g_h2 [BS_*D_];
__device__ float g_h3 [BS_*D_];
__device__ float g_t  [(size_t)BS_*ID_];        // 64 MB
__device__ float g_c0;                          // adjacency constant logit
// tf32-rounded TRANSPOSED ([N][K]) weight copies
__device__ float g_wq [D_*D_];
__device__ float g_wk [D_*D_];
__device__ float g_wv [D_*D_];
__device__ float g_wo [D_*D_];
__device__ float g_wg [D_*D_];
__device__ float g_wi [(size_t)D_*ID_];
__device__ float g_wo2[(size_t)ID_*D_];

// ---------------- tf32 helpers ----------------------------------------------
__device__ __forceinline__ unsigned f2tf(float f) {
    unsigned u;
    asm("cvt.rna.tf32.f32 %0, %1;" : "=r"(u) : "f"(f));
    return u;
}
__device__ __forceinline__ float rtf(float f) { return __uint_as_float(f2tf(f)); }

__device__ __forceinline__ void mma_tf32(float* c, const unsigned* a, const unsigned* b) {
    asm volatile(
        "mma.sync.aligned.m16n8k8.row.col.f32.tf32.tf32.f32 "
        "{%0,%1,%2,%3}, {%4,%5,%6,%7}, {%8,%9}, {%0,%1,%2,%3};"
        : "+f"(c[0]), "+f"(c[1]), "+f"(c[2]), "+f"(c[3])
        : "r"(a[0]), "r"(a[1]), "r"(a[2]), "r"(a[3]), "r"(b[0]), "r"(b[1]));
}

__device__ __forceinline__ void cpa16(unsigned s, const void* g) {
    asm volatile("cp.async.cg.shared.global [%0], [%1], 16;" :: "r"(s), "l"(g));
}

// fragment loader (verified R12 bit-identical). Lanes 0-15 address rows at kk,
// lanes 16-31 rows at kk+4: r0=(rows0-7,kk), r1=(rows8-15,kk),
// r2=(rows0-7,kk+4), r3=(rows8-15,kk+4); thread i gets element (i/4, i%4).
__device__ __forceinline__ void ldsm_x4(unsigned* r, uint32_t addr) {
    asm volatile(
        "ldmatrix.sync.aligned.m8n8.x4.shared.b16 {%0,%1,%2,%3}, [%4];"
        : "=r"(r[0]), "=r"(r[1]), "=r"(r[2]), "=r"(r[3]) : "r"(addr));
}

// ---------------- weight transpose + tf32 round: out[n*K+k]=rtf(in[k*N+n]) --
__global__ void cvtt_k(const float* __restrict__ in, float* __restrict__ out,
                       int K, int N) {
    __shared__ float tile[32][33];
    int nb = blockIdx.x * 32, kb = blockIdx.y * 32;
    int tx = threadIdx.x & 31, ty = threadIdx.x >> 5;   // 32 x 8
#pragma unroll
    for (int i = 0; i < 4; i++)
        tile[ty + i * 8][tx] = in[(size_t)(kb + ty + i * 8) * N + nb + tx];
    __syncthreads();
#pragma unroll
    for (int i = 0; i < 4; i++)
        out[(size_t)(nb + ty + i * 8) * K + kb + tx] = rtf(tile[tx][ty + i * 8]);
}

// ---------------- RMSNorm (output tf32-rounded: feeds GEMMs only) -----------
__global__ void rmsnorm_k(const float* __restrict__ x, const float* __restrict__ w,
                          float* __restrict__ y) {
    int row = blockIdx.x;
    const float* xr = x + (size_t)row * D_;
    float* yr = y + (size_t)row * D_;
    float s = 0.f;
    for (int c = threadIdx.x; c < D_; c += 256) { float v = xr[c]; s += v * v; }
    __shared__ float red[256];
    red[threadIdx.x] = s; __syncthreads();
    for (int o = 128; o > 0; o >>= 1) {
        if (threadIdx.x < o) red[threadIdx.x] += red[threadIdx.x + o];
        __syncthreads();
    }
    float inv = rsqrtf(red[0] / (float)D_ + 1e-6f);
    for (int c = threadIdx.x; c < D_; c += 256) yr[c] = rtf(xr[c] * inv * w[c]);
}

// ---------------- TF32 GEMM core -------------------------------------------
// BT=1: B is [N][K] K-major (transposed weights) -> B tile [128][36], ldsm.
// BT=0: B is [K][N] n-major (activations)       -> B tile [32][136], scalar.
#define LDA_S 36
#define NSTG  3
#define BSTG0 (32 * 136)
#define BSTG1 (128 * 36)
#define TG_SMEM0 (NSTG * (128 * LDA_S + BSTG0) * 4)
#define TG_SMEM1 (NSTG * (128 * LDA_S + BSTG1) * 4)

template<int EPI, int RC, int DUAL, int BT>
__device__ __forceinline__ void gemm_core(
    int K,
    const float* __restrict__ A, int lda,
    const float* __restrict__ B, int ldb,
    float* __restrict__ C, int ldc,
    const float* __restrict__ R, int ldr,
    float* __restrict__ C2,
    float* smem, int brow, int bcol) {
    constexpr int BM = 128, BK = 32;
    constexpr int BST = BT ? BSTG1 : BSTG0;
    float* As = smem;
    float* Bs = smem + NSTG * BM * LDA_S;
    unsigned sAb = (unsigned)__cvta_generic_to_shared(As);
    unsigned sBb = (unsigned)__cvta_generic_to_shared(Bs);

    int tid = threadIdx.x, lane = tid & 31, warp = tid >> 5;
    int wm = warp >> 2, wn = warp & 3;
    int lr = lane >> 2, lc = lane & 3;
    int lane15 = lane & 15;
    int khalf = (lane >> 4) * 4;

    float acc[4][4][4];
#pragma unroll
    for (int mt = 0; mt < 4; mt++)
#pragma unroll
        for (int nt = 0; nt < 4; nt++)
#pragma unroll
            for (int i = 0; i < 4; i++) acc[mt][nt][i] = 0.f;

    int ntile = K / BK;

    auto issue = [&](int kt, int st) {
        int soa = st * BM * LDA_S, sob = st * BST;
#pragma unroll
        for (int i = 0; i < 4; i++) {
            int ch = tid + i * 256;
            int r = ch >> 3, c = ch & 7;
            cpa16(sAb + (unsigned)(soa + r * LDA_S + c * 4) * 4,
                  A + (size_t)(brow + r) * lda + kt * BK + c * 4);
            if (BT) {
                cpa16(sBb + (unsigned)(sob + r * 36 + c * 4) * 4,
                      B + (size_t)(bcol + r) * ldb + kt * BK + c * 4);
            } else {
                int rb = ch >> 5, cb = ch & 31;
                cpa16(sBb + (unsigned)(sob + rb * 136 + cb * 4) * 4,
                      B + (size_t)(kt * BK + rb) * ldb + bcol + cb * 4);
            }
        }
    };

    issue(0, 0);
    asm volatile("cp.async.commit_group;" ::: "memory");
    if (ntile > 1) {
        issue(1, 1);
        asm volatile("cp.async.commit_group;" ::: "memory");
    }

    for (int it = 0; it < ntile; it++) {
        int cur = it % NSTG;
        // race-free wait: final iteration drains everything.
        if (it < ntile - 1) {
            asm volatile("cp.async.wait_group 1;" ::: "memory");
        } else {
            asm volatile("cp.async.wait_group 0;" ::: "memory");
        }
        __syncthreads();

        unsigned aStage = sAb + (unsigned)(cur * BM * LDA_S) * 4;
        unsigned bStage = sBb + (unsigned)(cur * BST) * 4;
        const float* Bc = Bs + cur * BST;
#pragma unroll
        for (int ks = 0; ks < 4; ks++) {
            int kk = ks * 8;
            unsigned af[4][4], bf[4][2];
#pragma unroll
            for (int mt = 0; mt < 4; mt++) {
                int r = wm * 64 + mt * 16 + lane15;
                ldsm_x4(af[mt], aStage + (unsigned)(r * LDA_S + kk + khalf) * 4);
            }
            if (BT) {
                unsigned bq[2][4];
#pragma unroll
                for (int ntp = 0; ntp < 2; ntp++) {
                    int n = wn * 32 + ntp * 16 + lane15;
                    ldsm_x4(bq[ntp], bStage + (unsigned)(n * 36 + kk + khalf) * 4);
                }
                bf[0][0] = bq[0][0]; bf[0][1] = bq[0][2];
                bf[1][0] = bq[0][1]; bf[1][1] = bq[0][3];
                bf[2][0] = bq[1][0]; bf[2][1] = bq[1][2];
                bf[3][0] = bq[1][1]; bf[3][1] = bq[1][3];
            } else {
#pragma unroll
                for (int nt = 0; nt < 4; nt++) {
                    int c = wn * 32 + nt * 8 + lr;
                    const unsigned* p = (const unsigned*)&Bc[(kk + lc) * 136 + c];
                    bf[nt][0] = p[0];
                    bf[nt][1] = p[4 * 136];
                }
            }
#pragma unroll
            for (int mt = 0; mt < 4; mt++)
#pragma unroll
                for (int nt = 0; nt < 4; nt++)
                    mma_tf32(acc[mt][nt], af[mt], bf[nt]);
        }

        int nx = it + 2;
        if (nx < ntile) {
            issue(nx, nx % NSTG);
            asm volatile("cp.async.commit_group;" ::: "memory");
        }
    }

#pragma unroll
    for (int mt = 0; mt < 4; mt++) {
        int r0 = brow + wm * 64 + mt * 16 + lr;
#pragma unroll
        for (int nt = 0; nt < 4; nt++) {
            int c0 = bcol + wn * 32 + nt * 8 + 2 * lc;
#pragma unroll
            for (int half = 0; half < 2; half++) {
                size_t row = (size_t)(r0 + half * 8);
                float v0 = acc[mt][nt][half * 2 + 0];
                float v1 = acc[mt][nt][half * 2 + 1];
                if (EPI == 2 || EPI == 3) {
                    v0 = v0 / (1.f + __expf(-v0));
                    v1 = v1 / (1.f + __expf(-v1));
                }
                if (EPI == 1 || EPI == 3) {
                    v0 += R[row * ldr + c0];
                    v1 += R[row * ldr + c0 + 1];
                }
                float s0 = RC ? rtf(v0) : v0;
                float s1 = RC ? rtf(v1) : v1;
                float2 st = { s0, s1 };
                *(float2*)(C + row * ldc + c0) = st;
                if (DUAL) {
                    float2 st2 = { rtf(v0), rtf(v1) };
                    *(float2*)(C2 + row * ldc + c0) = st2;
                }
            }
        }
    }
}

template<int EPI, int RC, int DUAL, int BT>
__global__ __launch_bounds__(256, 2)
void tgemm_k(int M, int N, int K,
             const float* __restrict__ A, int lda, long long sA,
             const float* __restrict__ B, int ldb, long long sB,
             float* __restrict__ C, int ldc, long long sC,
             const float* __restrict__ R, int ldr, long long sR,
             float* __restrict__ C2) {
    extern __shared__ float smem[];
    int bz = blockIdx.z;
    A += (size_t)bz * sA; B += (size_t)bz * sB; C += (size_t)bz * sC;
    if (EPI == 1 || EPI == 3) R += (size_t)bz * sR;
    gemm_core<EPI, RC, DUAL, BT>(K, A, lda, B, ldb, C, ldc, R, ldr, C2,
                                 smem, blockIdx.y * 128, blockIdx.x * 128);
}

// batched QKV: one launch, grid.z selects (weight, output); V output rounded
__global__ __launch_bounds__(256, 2)
void qkv_k(const float* __restrict__ A,
           const float* __restrict__ B0, const float* __restrict__ B1,
           const float* __restrict__ B2,
           float* __restrict__ C0, float* __restrict__ C1, float* __restrict__ C2o) {
    extern __shared__ float smem[];
    int bz = blockIdx.z;
    const float* B = (bz == 0) ? B0 : (bz == 1) ? B1 : B2;
    float* C = (bz == 0) ? C0 : (bz == 1) ? C1 : C2o;
    if (bz == 2)
        gemm_core<0, 1, 0, 1>(D_, A, D_, B, D_, C, D_, nullptr, 0, nullptr,
                              smem, blockIdx.y * 128, blockIdx.x * 128);
    else
        gemm_core<0, 0, 0, 1>(D_, A, D_, B, D_, C, D_, nullptr, 0, nullptr,
                              smem, blockIdx.y * 128, blockIdx.x * 128);
}

// ---------------- RoPE (in-place, outputs tf32-rounded for MMA scores) ------
__global__ void rope_k(float* __restrict__ q, float* __restrict__ k) {
    int idx = blockIdx.x * 256 + threadIdx.x;
    int r = idx & 31;
    int h = (idx >> 5) & (NH - 1);
    int s = (idx >> 10) & (S_ - 1);
    int b = idx >> 20;
    float inv = powf(10000.f, -(float)(2 * r) / (float)HDIM);
    float ang = (float)s * inv;
    float sn, cs;
    sincosf(ang, &sn, &cs);
    size_t base = ((size_t)(b * S_ + s)) * D_ + h * HDIM;
    float q0 = q[base + r], q1 = q[base + r + 32];
    q[base + r]      = rtf(q0 * cs - q1 * sn);
    q[base + r + 32] = rtf(q1 * cs + q0 * sn);
    float k0 = k[base + r], k1 = k[base + r + 32];
    k[base + r]      = rtf(k0 * cs - k1 * sn);
    k[base + r + 32] = rtf(k1 * cs + k0 * sn);
}

// ---------------- scores via tf32 MMA: packed lower-triangle grid -----------
#define SC_LD 68
#define SC_SMEM (2 * 128 * SC_LD * 4)

__global__ __launch_bounds__(256)
void scores_mma_k(const float* __restrict__ q, const float* __restrict__ k,
                  float* __restrict__ attn) {
    int bh = blockIdx.y;
    int b = bh >> 5, h = bh & 31;
    int t = blockIdx.x;
    int ib = 0;
    while ((ib + 1) * (ib + 2) / 2 <= t) ib++;
    int jb = t - ib * (ib + 1) / 2;
    extern __shared__ float smem[];
    float* Qs = smem;
    float* Ks = smem + 128 * SC_LD;
    unsigned sQb = (unsigned)__cvta_generic_to_shared(Qs);
    unsigned sKb = (unsigned)__cvta_generic_to_shared(Ks);
    const float* qb = q + ((size_t)b * S_ + ib * 128) * D_ + h * HDIM;
    const float* kb = k + ((size_t)b * S_ + jb * 128) * D_ + h * HDIM;
    int tid = threadIdx.x;
#pragma unroll
    for (int i = 0; i < 8; i++) {
        int ch = tid + i * 256;
        int r = ch >> 4, c = (ch & 15) * 4;
        *(float4*)&Qs[r * SC_LD + c] = *(const float4*)(qb + (size_t)r * D_ + c);
        *(float4*)&Ks[r * SC_LD + c] = *(const float4*)(kb + (size_t)r * D_ + c);
    }
    __syncthreads();
    int lane = tid & 31, warp = tid >> 5;
    int wm = warp >> 2, wn = warp & 3;
    int lr = lane >> 2, lc = lane & 3;
    int lane15 = lane & 15, khalf = (lane >> 4) * 4;
    float acc[4][4][4];
#pragma unroll
    for (int mt = 0; mt < 4; mt++)
#pragma unroll
        for (int nt = 0; nt < 4; nt++)
#pragma unroll
            for (int i = 0; i < 4; i++) acc[mt][nt][i] = 0.f;
#pragma unroll
    for (int ks = 0; ks < 8; ks++) {
        int kk = ks * 8;
        unsigned af[4][4], bf[4][2], bq[2][4];
#pragma unroll
        for (int mt = 0; mt < 4; mt++) {
            int r = wm * 64 + mt * 16 + lane15;
            ldsm_x4(af[mt], sQb + (unsigned)(r * SC_LD + kk + khalf) * 4);
        }
#pragma unroll
        for (int ntp = 0; ntp < 2; ntp++) {
            int n = wn * 32 + ntp * 16 + lane15;
            ldsm_x4(bq[ntp], sKb + (unsigned)(n * SC_LD + kk + khalf) * 4);
        }
        bf[0][0] = bq[0][0]; bf[0][1] = bq[0][2];
        bf[1][0] = bq[0][1]; bf[1][1] = bq[0][3];
        bf[2][0] = bq[1][0]; bf[2][1] = bq[1][2];
        bf[3][0] = bq[1][1]; bf[3][1] = bq[1][3];
#pragma unroll
        for (int mt = 0; mt < 4; mt++)
#pragma unroll
            for (int nt = 0; nt < 4; nt++)
                mma_tf32(acc[mt][nt], af[mt], bf[nt]);
    }
    float* ob = attn + (size_t)bh * S_ * S_;
#pragma unroll
    for (int mt = 0; mt < 4; mt++) {
        int r0 = ib * 128 + wm * 64 + mt * 16 + lr;
#pragma unroll
        for (int nt = 0; nt < 4; nt++) {
            int c0 = jb * 128 + wn * 32 + nt * 8 + 2 * lc;
#pragma unroll
            for (int half = 0; half < 2; half++) {
                float2 st = { acc[mt][nt][half * 2 + 0] * 0.125f,
                              acc[mt][nt][half * 2 + 1] * 0.125f };
                *(float2*)(ob + (size_t)(r0 + half * 8) * S_ + c0) = st;
            }
        }
    }
}

// ---------------- causal softmax -------------------------------------------
__global__ __launch_bounds__(256)
void softmax_k(float* __restrict__ attn) {
    size_t row = blockIdx.x;
    int i = (int)(row & (S_ - 1));
    float* p = attn + row * S_;
    int len = i + 1;
    int blockend = ((i >> 7) + 1) << 7;
    int tid = threadIdx.x;
    __shared__ float sh[8];
    float x[4];
#pragma unroll
    for (int jt = 0; jt < 4; jt++) {
        int j = tid + jt * 256;
        x[jt] = (j < len) ? p[j] : -3.4e38f;
    }
    float m = fmaxf(fmaxf(x[0], x[1]), fmaxf(x[2], x[3]));
#pragma unroll
    for (int o = 16; o > 0; o >>= 1) m = fmaxf(m, __shfl_xor_sync(~0u, m, o));
    if ((tid & 31) == 0) sh[tid >> 5] = m;
    __syncthreads();
    m = sh[0];
#pragma unroll
    for (int z = 1; z < 8; z++) m = fmaxf(m, sh[z]);
    __syncthreads();
    float e[4], s = 0.f;
#pragma unroll
    for (int jt = 0; jt < 4; jt++) {
        int j = tid + jt * 256;
        e[jt] = (j < len) ? __expf(x[jt] - m) : 0.f;
        s += e[jt];
    }
#pragma unroll
    for (int o = 16; o > 0; o >>= 1) s += __shfl_xor_sync(~0u, s, o);
    if ((tid & 31) == 0) sh[tid >> 5] = s;
    __syncthreads();
    s = sh[0];
#pragma unroll
    for (int z = 1; z < 8; z++) s += sh[z];
    float inv = 1.f / s;
#pragma unroll
    for (int jt = 0; jt < 4; jt++) {
        int j = tid + jt * 256;
        if (j < blockend) p[j] = rtf(e[jt] * inv);
    }
}

// ---------------- attn @ V via tf32 MMA (causal K truncation) ---------------
__global__ __launch_bounds__(256)
void av_mma_k(const float* __restrict__ attn, const float* __restrict__ v,
              float* __restrict__ ao) {
    constexpr int ALD = 36, BLD = 72;
    __shared__ float As[2][128 * ALD];
    __shared__ float Bs[2][32 * BLD];
    unsigned sAb = (unsigned)__cvta_generic_to_shared(&As[0][0]);
    unsigned sBb = (unsigned)__cvta_generic_to_shared(&Bs[0][0]);
    int bh = blockIdx.y;
    int b = bh >> 5, h = bh & 31;
    int ib = blockIdx.x;
    const float* ab = attn + (size_t)bh * S_ * S_ + (size_t)ib * 128 * S_;
    const float* vb = v + (size_t)b * S_ * D_ + h * HDIM;
    int tid = threadIdx.x, lane = tid & 31, warp = tid >> 5;
    int wm = warp >> 1, wn = warp & 1;
    int lr = lane >> 2, lc = lane & 3;
    int lane15 = lane & 15, khalf = (lane >> 4) * 4;
    int ntile = (ib + 1) * 4;

    auto issue = [&](int kt, int st) {
#pragma unroll
        for (int i = 0; i < 4; i++) {
            int ch = tid + i * 256;
            int r = ch >> 3, c = ch & 7;
            cpa16(sAb + (unsigned)(st * 128 * ALD + r * ALD + c * 4) * 4,
                  ab + (size_t)r * S_ + kt * 32 + c * 4);
        }
#pragma unroll
        for (int i = 0; i < 2; i++) {
            int ch = tid + i * 256;
            int r = ch >> 4, c = ch & 15;
            cpa16(sBb + (unsigned)(st * 32 * BLD + r * BLD + c * 4) * 4,
                  vb + (size_t)(kt * 32 + r) * D_ + c * 4);
        }
    };

    float acc[2][4][4];
#pragma unroll
    for (int mt = 0; mt < 2; mt++)
#pragma unroll
        for (int nt = 0; nt < 4; nt++)
#pragma unroll
            for (int i = 0; i < 4; i++) acc[mt][nt][i] = 0.f;

    issue(0, 0);
    asm volatile("cp.async.commit_group;" ::: "memory");
    for (int it = 0; it < ntile; it++) {
        int cur = it & 1;
        if (it + 1 < ntile) {
            issue(it + 1, cur ^ 1);
            asm volatile("cp.async.commit_group;" ::: "memory");
            asm volatile("cp.async.wait_group 1;" ::: "memory");
        } else {
            asm volatile("cp.async.wait_group 0;" ::: "memory");
        }
        __syncthreads();
        unsigned aStage = sAb + (unsigned)(cur * 128 * ALD) * 4;
#pragma unroll
        for (int ks = 0; ks < 4; ks++) {
            int kk = ks * 8;
            unsigned af[2][4], bf[4][2];
#pragma unroll
            for (int mt = 0; mt < 2; mt++) {
                int r = wm * 32 + mt * 16 + lane15;
                ldsm_x4(af[mt], aStage + (unsigned)(r * ALD + kk + khalf) * 4);
            }
#pragma unroll
            for (int nt = 0; nt < 4; nt++) {
                int c = wn * 32 + nt * 8 + lr;
                const unsigned* p = (const unsigned*)&Bs[cur][(kk + lc) * BLD + c];
                bf[nt][0] = p[0];
                bf[nt][1] = p[4 * BLD];
            }
#pragma unroll
            for (int mt = 0; mt < 2; mt++)
#pragma unroll
                for (int nt = 0; nt < 4; nt++)
                    mma_tf32(acc[mt][nt], af[mt], bf[nt]);
        }
        __syncthreads();
    }
#pragma unroll
    for (int mt = 0; mt < 2; mt++) {
        int r0 = ib * 128 + wm * 32 + mt * 16 + lr;
#pragma unroll
        for (int nt = 0; nt < 4; nt++) {
            int c0 = wn * 32 + nt * 8 + 2 * lc;
#pragma unroll
            for (int half = 0; half < 2; half++) {
                size_t row = (size_t)(b * S_ + r0 + half * 8);
                float2 st = { rtf(acc[mt][nt][half * 2 + 0]),
                              rtf(acc[mt][nt][half * 2 + 1]) };
                *(float2*)(ao + row * D_ + h * HDIM + c0) = st;
            }
        }
    }
}

// ---------------- adjacency constant for masked pairs ------------------------
__global__ void c0_k(const float* __restrict__ b1, const float* __restrict__ W2,
                     const float* __restrict__ b2) {
    int t = threadIdx.x;
    float v = fmaxf(b1[t], 0.f) * W2[t];
#pragma unroll
    for (int o = 16; o > 0; o >>= 1) v += __shfl_xor_sync(~0u, v, o);
    __shared__ float sh[2];
    if ((t & 31) == 0) sh[t >> 5] = v;
    __syncthreads();
    if (t == 0) g_c0 = b2[0] + sh[0] + sh[1];
}

__global__ void adjfill_k(float* __restrict__ adj) {
    int i = blockIdx.x, b = blockIdx.y;
    int start = ((i >> 7) + 1) << 7;
    if (start >= S_) return;
    float val = rtf(1.f / (1.f + __expf(-g_c0)));
    float* p = adj + ((size_t)b * S_ + i) * S_;
    for (int j = start + threadIdx.x; j < S_; j += 128) p[j] = val;
}

// ---------------- adjacency MLP via tf32 MMA (lower tiles only) -------------
__global__ __launch_bounds__(256)
void adj_mma_k(const float* __restrict__ attn,
               const float* __restrict__ W1, const float* __restrict__ b1,
               const float* __restrict__ W2, const float* __restrict__ b2,
               float* __restrict__ adj) {
    constexpr int ALD = 36, WLD = 72;
    int jt = blockIdx.x, i = blockIdx.y, b = blockIdx.z;
    if (jt > (i >> 7)) return;
    __shared__ float As[128 * ALD];
    __shared__ float Ws[32 * WLD];
    __shared__ float sb1[AH_], sw2[AH_];
    int tid = threadIdx.x;
#pragma unroll
    for (int it = 0; it < 8; it++) {
        int idx = tid + it * 256;
        Ws[(idx >> 6) * WLD + (idx & 63)] = rtf(W1[idx]);
    }
    if (tid < AH_) { sb1[tid] = b1[tid]; sw2[tid] = W2[tid]; }
#pragma unroll
    for (int it = 0; it < 4; it++) {
        int ch = tid + it * 256;
        int h = ch >> 5, jq = ch & 31;
        float4 a4 = *(const float4*)(attn +
            (((size_t)(b * NH + h) * S_ + i) * S_) + jt * 128 + jq * 4);
        As[(jq * 4 + 0) * ALD + h] = a4.x;
        As[(jq * 4 + 1) * ALD + h] = a4.y;
        As[(jq * 4 + 2) * ALD + h] = a4.z;
        As[(jq * 4 + 3) * ALD + h] = a4.w;
    }
    __syncthreads();
    int lane = tid & 31, warp = tid >> 5;
    int lr = lane >> 2, lc = lane & 3;
    float acc[8][4];
#pragma unroll
    for (int nt = 0; nt < 8; nt++)
#pragma unroll
        for (int z = 0; z < 4; z++) acc[nt][z] = 0.f;
#pragma unroll
    for (int ks = 0; ks < 4; ks++) {
        int kk = ks * 8;
        unsigned af[4];
        int r = warp * 16 + lr;
        const unsigned* p = (const unsigned*)&As[r * ALD + kk + lc];
        af[0] = p[0];
        af[1] = p[8 * ALD];
        af[2] = p[4];
        af[3] = p[8 * ALD + 4];
#pragma unroll
        for (int nt = 0; nt < 8; nt++) {
            int c = nt * 8 + lr;
            const unsigned* q = (const unsigned*)&Ws[(kk + lc) * WLD + c];
            unsigned bf[2] = { q[0], q[4 * WLD] };
            mma_tf32(acc[nt], af, bf);
        }
    }
    float s0 = 0.f, s1 = 0.f;
#pragma unroll
    for (int nt = 0; nt < 8; nt++) {
        int c0 = nt * 8 + 2 * lc, c1 = c0 + 1;
        s0 += fmaxf(acc[nt][0] + sb1[c0], 0.f) * sw2[c0]
            + fmaxf(acc[nt][1] + sb1[c1], 0.f) * sw2[c1];
        s1 += fmaxf(acc[nt][2] + sb1[c0], 0.f) * sw2[c0]
            + fmaxf(acc[nt][3] + sb1[c1], 0.f) * sw2[c1];
    }
    s0 += __shfl_xor_sync(~0u, s0, 1); s0 += __shfl_xor_sync(~0u, s0, 2);
    s1 += __shfl_xor_sync(~0u, s1, 1); s1 += __shfl_xor_sync(~0u, s1, 2);
    if (lc == 0) {
        float bb = b2[0];
        int j0 = jt * 128 + warp * 16;
        size_t base = ((size_t)b * S_ + i) * S_;
        adj[base + j0 + lr]     = rtf(1.f / (1.f + __expf(-(s0 + bb))));
        adj[base + j0 + lr + 8] = rtf(1.f / (1.f + __expf(-(s1 + bb))));
    }
}

// ---------------- launch ----------------------------------------------------
extern "C" void kernel_launch(void* const* d_in, const int* in_sizes, int n_in,
                              void* d_out, int out_size) {
    const float* x        = (const float*)d_in[0];
    const float* w_q      = (const float*)d_in[1];
    const float* w_k      = (const float*)d_in[2];
    const float* w_v      = (const float*)d_in[3];
    const float* w_o      = (const float*)d_in[4];
    const float* norm1_w  = (const float*)d_in[5];
    const float* norm2_w  = (const float*)d_in[6];
    const float* w_adj1   = (const float*)d_in[7];
    const float* b_adj1   = (const float*)d_in[8];
    const float* w_adj2   = (const float*)d_in[9];
    const float* b_adj2   = (const float*)d_in[10];
    const float* w_gnn    = (const float*)d_in[11];
    const float* w_mlp_in = (const float*)d_in[12];
    const float* w_mlp_out= (const float*)d_in[13];

    float *h, *q, *k, *v, *attn, *ao, *h1, *h1t, *adj, *msg, *h2, *h3, *t;
    float *wq, *wk, *wv, *wo, *wg, *wi, *wo2;
    cudaGetSymbolAddress((void**)&h,    g_h);
    cudaGetSymbolAddress((void**)&q,    g_q);
    cudaGetSymbolAddress((void**)&k,    g_k);
    cudaGetSymbolAddress((void**)&v,    g_v);
    cudaGetSymbolAddress((void**)&attn, g_attn);
    cudaGetSymbolAddress((void**)&ao,   g_ao);
    cudaGetSymbolAddress((void**)&h1,   g_h1);
    cudaGetSymbolAddress((void**)&h1t,  g_h1t);
    cudaGetSymbolAddress((void**)&adj,  g_adj);
    cudaGetSymbolAddress((void**)&msg,  g_msg);
    cudaGetSymbolAddress((void**)&h2,   g_h2);
    cudaGetSymbolAddress((void**)&h3,   g_h3);
    cudaGetSymbolAddress((void**)&t,    g_t);
    cudaGetSymbolAddress((void**)&wq,   g_wq);
    cudaGetSymbolAddress((void**)&wk,   g_wk);
    cudaGetSymbolAddress((void**)&wv,   g_wv);
    cudaGetSymbolAddress((void**)&wo,   g_wo);
    cudaGetSymbolAddress((void**)&wg,   g_wg);
    cudaGetSymbolAddress((void**)&wi,   g_wi);
    cudaGetSymbolAddress((void**)&wo2,  g_wo2);

    cudaFuncSetAttribute(qkv_k,            cudaFuncAttributeMaxDynamicSharedMemorySize, TG_SMEM1);
    cudaFuncSetAttribute(tgemm_k<1,0,1,1>, cudaFuncAttributeMaxDynamicSharedMemorySize, TG_SMEM1);
    cudaFuncSetAttribute(tgemm_k<3,0,0,1>, cudaFuncAttributeMaxDynamicSharedMemorySize, TG_SMEM1);
    cudaFuncSetAttribute(tgemm_k<2,1,0,1>, cudaFuncAttributeMaxDynamicSharedMemorySize, TG_SMEM1);
    cudaFuncSetAttribute(tgemm_k<1,0,0,1>, cudaFuncAttributeMaxDynamicSharedMemorySize, TG_SMEM1);
    cudaFuncSetAttribute(tgemm_k<0,1,0,0>, cudaFuncAttributeMaxDynamicSharedMemorySize, TG_SMEM0);
    cudaFuncSetAttribute(scores_mma_k,     cudaFuncAttributeMaxDynamicSharedMemorySize, SC_SMEM);

    // transpose + tf32-round all weights: wT[n*K+k] = rtf(w[k*N+n])
    cvtt_k<<<dim3(64, 64),  256>>>(w_q,       wq,  D_,  D_);
    cvtt_k<<<dim3(64, 64),  256>>>(w_k,       wk,  D_,  D_);
    cvtt_k<<<dim3(64, 64),  256>>>(w_v,       wv,  D_,  D_);
    cvtt_k<<<dim3(64, 64),  256>>>(w_o,       wo,  D_,  D_);
    cvtt_k<<<dim3(64, 64),  256>>>(w_gnn,     wg,  D_,  D_);
    cvtt_k<<<dim3(256, 64), 256>>>(w_mlp_in,  wi,  D_,  ID_);
    cvtt_k<<<dim3(64, 256), 256>>>(w_mlp_out, wo2, ID_, D_);

    // adjacency constant (for fully-masked pairs)
    c0_k<<<1, 64>>>(b_adj1, w_adj2, b_adj2);

    // h = rmsnorm(x, norm1)  (tf32-rounded)
    rmsnorm_k<<<BS_, 256>>>(x, norm1_w, h);

    // q/k/v = h @ W   (one batched launch; BT weights; v rounded)
    qkv_k<<<dim3(16, 16, 3), 256, TG_SMEM1>>>(h, wq, wk, wv, q, k, v);

    // RoPE in place (rounded)
    rope_k<<<(B_ * S_ * NH * 32) / 256, 256>>>(q, k);

    // scores (MMA, packed lower-triangle grid, B-ldsm) + causal softmax
    scores_mma_k<<<dim3(36, B_ * NH), 256, SC_SMEM>>>(q, k, attn);
    softmax_k<<<B_ * NH * S_, 256>>>(attn);

    // attn @ V  (MMA, ao rounded)
    av_mma_k<<<dim3(8, B_ * NH), 256>>>(attn, v, ao);

    // h1 = x + ao @ w_o   (BT; exact h1 + rounded h1t)
    tgemm_k<1,0,1,1><<<dim3(16, 16), 256, TG_SMEM1>>>(BS_, D_, D_, ao, D_, 0, wo, D_, 0,
                                                      h1, D_, 0, x, D_, 0, h1t);

    // adjacency: constant fill for masked region + MMA on lower tiles
    adjfill_k<<<dim3(S_, B_), 128>>>(adj);
    adj_mma_k<<<dim3(8, S_, B_), 256>>>(attn, w_adj1, b_adj1, w_adj2, b_adj2, adj);

    // msg = adj @ h1t  (activation B: scalar path)
    tgemm_k<0,1,0,0><<<dim3(16, 8, B_), 256, TG_SMEM0>>>(S_, D_, S_,
        adj, S_, (long long)S_ * S_,
        h1t, D_, (long long)S_ * D_,
        msg, D_, (long long)S_ * D_, nullptr, 0, 0, nullptr);

    // h2 = h1 + silu(msg @ w_gnn)  (BT)
    tgemm_k<3,0,0,1><<<dim3(16, 16), 256, TG_SMEM1>>>(BS_, D_, D_, msg, D_, 0, wg, D_, 0,
                                                      h2, D_, 0, h1, D_, 0, nullptr);

    // h3 = rmsnorm(h2, norm2)  (rounded)
    rmsnorm_k<<<BS_, 256>>>(h2, norm2_w, h3);

    // t = silu(h3 @ w_mlp_in)  (BT; rounded: feeds mlp_out)
    tgemm_k<2,1,0,1><<<dim3(64, 16), 256, TG_SMEM1>>>(BS_, ID_, D_, h3, D_, 0, wi, D_, 0,
                                                      t, ID_, 0, nullptr, 0, 0, nullptr);

    // out = h2 + t @ w_mlp_out  (BT)
    tgemm_k<1,0,0,1><<<dim3(16, 16), 256, TG_SMEM1>>>(BS_, D_, ID_, t, ID_, 0, wo2, ID_, 0,
                                                      (float*)d_out, D_, 0, h2, D_, 0, nullptr);
}

// round 17
// speedup vs baseline: 1.1779x; 1.1779x over previous
#include <cuda_runtime.h>
#include <stdint.h>
#include <math.h>

#define B_   2
#define S_   1024
#define D_   2048
#define NH   32
#define HDIM 64
#define ID_  8192
#define AH_  64
#define BS_  (B_*S_)

// ---------------- scratch (device globals; no runtime allocation) ----------
__device__ float g_h  [BS_*D_];
__device__ float g_q  [BS_*D_];
__device__ float g_k  [BS_*D_];
__device__ float g_v  [BS_*D_];
__device__ float g_attn[(size_t)B_*NH*S_*S_];   // 256 MB
__device__ float g_ao [BS_*D_];
__device__ float g_h1 [BS_*D_];
__device__ float g_h1t[BS_*D_];
__device__ float g_adj[(size_t)B_*S_*S_];
__device__ float g_msg[BS_*D_];
__device__ float g_h2 [BS_*D_];
__device__ float g_h3 [BS_*D_];
__device__ float g_t  [(size_t)BS_*ID_];        // 64 MB
__device__ float g_c0;                          // adjacency constant logit
// tf32-rounded weight copies
__device__ float g_wq [D_*D_];
__device__ float g_wk [D_*D_];
__device__ float g_wv [D_*D_];
__device__ float g_wo [D_*D_];
__device__ float g_wg [D_*D_];
__device__ float g_wi [(size_t)D_*ID_];
__device__ float g_wo2[(size_t)ID_*D_];

// ---------------- tf32 helpers ----------------------------------------------
__device__ __forceinline__ unsigned f2tf(float f) {
    unsigned u;
    asm("cvt.rna.tf32.f32 %0, %1;" : "=r"(u) : "f"(f));
    return u;
}
__device__ __forceinline__ float rtf(float f) { return __uint_as_float(f2tf(f)); }

__device__ __forceinline__ void mma_tf32(float* c, const unsigned* a, const unsigned* b) {
    asm volatile(
        "mma.sync.aligned.m16n8k8.row.col.f32.tf32.tf32.f32 "
        "{%0,%1,%2,%3}, {%4,%5,%6,%7}, {%8,%9}, {%0,%1,%2,%3};"
        : "+f"(c[0]), "+f"(c[1]), "+f"(c[2]), "+f"(c[3])
        : "r"(a[0]), "r"(a[1]), "r"(a[2]), "r"(a[3]), "r"(b[0]), "r"(b[1]));
}

__device__ __forceinline__ void cpa16(unsigned s, const void* g) {
    asm volatile("cp.async.cg.shared.global [%0], [%1], 16;" :: "r"(s), "l"(g));
}

// fragment loader (verified R12 bit-identical). r0=(rows0-7,kk),
// r1=(rows8-15,kk), r2=(rows0-7,kk+4), r3=(rows8-15,kk+4);
// thread i gets element (i/4, i%4) of each 8x4-b32 tile.
__device__ __forceinline__ void ldsm_x4(unsigned* r, uint32_t addr) {
    asm volatile(
        "ldmatrix.sync.aligned.m8n8.x4.shared.b16 {%0,%1,%2,%3}, [%4];"
        : "=r"(r[0]), "=r"(r[1]), "=r"(r[2]), "=r"(r[3]) : "r"(addr));
}

// ---------------- fused weight tf32 pre-rounding (one launch) ---------------
__global__ void cvtw_all_k(const float* __restrict__ s0, float* __restrict__ d0,
                           const float* __restrict__ s1, float* __restrict__ d1,
                           const float* __restrict__ s2, float* __restrict__ d2,
                           const float* __restrict__ s3, float* __restrict__ d3,
                           const float* __restrict__ s4, float* __restrict__ d4,
                           const float* __restrict__ s5, float* __restrict__ d5,
                           const float* __restrict__ s6, float* __restrict__ d6) {
    int bb = blockIdx.x;
    const float* in;
    float* out;
    size_t off;
    if (bb < 20480) {
        int w = bb >> 12, lb = bb & 4095;
        in  = (w == 0) ? s0 : (w == 1) ? s1 : (w == 2) ? s2 : (w == 3) ? s3 : s4;
        out = (w == 0) ? d0 : (w == 1) ? d1 : (w == 2) ? d2 : (w == 3) ? d3 : d4;
        off = (size_t)lb * 1024;
    } else if (bb < 36864) {
        in = s5; out = d5; off = (size_t)(bb - 20480) * 1024;
    } else {
        in = s6; out = d6; off = (size_t)(bb - 36864) * 1024;
    }
    size_t i = off + (size_t)threadIdx.x * 4;
    float4 v = *(const float4*)(in + i);
    float4 o = { rtf(v.x), rtf(v.y), rtf(v.z), rtf(v.w) };
    *(float4*)(out + i) = o;
}

// ---------------- RMSNorm (output tf32-rounded: feeds GEMMs only) -----------
__global__ void rmsnorm_k(const float* __restrict__ x, const float* __restrict__ w,
                          float* __restrict__ y) {
    int row = blockIdx.x;
    const float* xr = x + (size_t)row * D_;
    float* yr = y + (size_t)row * D_;
    float s = 0.f;
    for (int c = threadIdx.x; c < D_; c += 256) { float v = xr[c]; s += v * v; }
    __shared__ float red[256];
    red[threadIdx.x] = s; __syncthreads();
    for (int o = 128; o > 0; o >>= 1) {
        if (threadIdx.x < o) red[threadIdx.x] += red[threadIdx.x + o];
        __syncthreads();
    }
    float inv = rsqrtf(red[0] / (float)D_ + 1e-6f);
    for (int c = threadIdx.x; c < D_; c += 256) yr[c] = rtf(xr[c] * inv * w[c]);
}

// ---------------- TF32 GEMM core: 3-stage cp.async, ldmatrix A frags --------
#define LDA_S 36
#define LDB_S 136
#define NSTG  3
#define TG_SMEM (NSTG * (128 * LDA_S + 32 * LDB_S) * 4)

template<int EPI, int RC, int DUAL>
__device__ __forceinline__ void gemm_core(
    int K,
    const float* __restrict__ A, int lda,
    const float* __restrict__ B, int ldb,
    float* __restrict__ C, int ldc,
    const float* __restrict__ R, int ldr,
    float* __restrict__ C2,
    float* smem, int brow, int bcol) {
    constexpr int BM = 128, BK = 32;
    float* As = smem;
    float* Bs = smem + NSTG * BM * LDA_S;
    unsigned sAb = (unsigned)__cvta_generic_to_shared(As);
    unsigned sBb = (unsigned)__cvta_generic_to_shared(Bs);

    int tid = threadIdx.x, lane = tid & 31, warp = tid >> 5;
    int wm = warp >> 2, wn = warp & 3;
    int lr = lane >> 2, lc = lane & 3;
    int lane15 = lane & 15;
    int khalf = (lane >> 4) * 4;

    float acc[4][4][4];
#pragma unroll
    for (int mt = 0; mt < 4; mt++)
#pragma unroll
        for (int nt = 0; nt < 4; nt++)
#pragma unroll
            for (int i = 0; i < 4; i++) acc[mt][nt][i] = 0.f;

    int ntile = K / BK;

    auto issue = [&](int kt, int st) {
        int soa = st * BM * LDA_S, sob = st * BK * LDB_S;
#pragma unroll
        for (int i = 0; i < 4; i++) {
            int ch = tid + i * 256;
            int r = ch >> 3, c = ch & 7;
            cpa16(sAb + (unsigned)(soa + r * LDA_S + c * 4) * 4,
                  A + (size_t)(brow + r) * lda + kt * BK + c * 4);
            int rb = ch >> 5, cb = ch & 31;
            cpa16(sBb + (unsigned)(sob + rb * LDB_S + cb * 4) * 4,
                  B + (size_t)(kt * BK + rb) * ldb + bcol + cb * 4);
        }
    };

    issue(0, 0);
    asm volatile("cp.async.commit_group;" ::: "memory");
    if (ntile > 1) {
        issue(1, 1);
        asm volatile("cp.async.commit_group;" ::: "memory");
    }

    for (int it = 0; it < ntile; it++) {
        int cur = it % NSTG;
        // race-free wait: final iteration drains everything.
        if (it < ntile - 1) {
            asm volatile("cp.async.wait_group 1;" ::: "memory");
        } else {
            asm volatile("cp.async.wait_group 0;" ::: "memory");
        }
        __syncthreads();

        unsigned aStage = sAb + (unsigned)(cur * BM * LDA_S) * 4;
        const float* Bc = Bs + cur * BK * LDB_S;
#pragma unroll
        for (int ks = 0; ks < 4; ks++) {
            int kk = ks * 8;
            unsigned af[4][4], bf[4][2];
#pragma unroll
            for (int mt = 0; mt < 4; mt++) {
                int r = wm * 64 + mt * 16 + lane15;
                ldsm_x4(af[mt], aStage + (unsigned)(r * LDA_S + kk + khalf) * 4);
            }
#pragma unroll
            for (int nt = 0; nt < 4; nt++) {
                int c = wn * 32 + nt * 8 + lr;
                const unsigned* p = (const unsigned*)&Bc[(kk + lc) * LDB_S + c];
                bf[nt][0] = p[0];
                bf[nt][1] = p[4 * LDB_S];
            }
#pragma unroll
            for (int mt = 0; mt < 4; mt++)
#pragma unroll
                for (int nt = 0; nt < 4; nt++)
                    mma_tf32(acc[mt][nt], af[mt], bf[nt]);
        }

        int nx = it + 2;
        if (nx < ntile) {
            issue(nx, nx % NSTG);
            asm volatile("cp.async.commit_group;" ::: "memory");
        }
    }

#pragma unroll
    for (int mt = 0; mt < 4; mt++) {
        int r0 = brow + wm * 64 + mt * 16 + lr;
#pragma unroll
        for (int nt = 0; nt < 4; nt++) {
            int c0 = bcol + wn * 32 + nt * 8 + 2 * lc;
#pragma unroll
            for (int half = 0; half < 2; half++) {
                size_t row = (size_t)(r0 + half * 8);
                float v0 = acc[mt][nt][half * 2 + 0];
                float v1 = acc[mt][nt][half * 2 + 1];
                if (EPI == 2 || EPI == 3) {
                    v0 = v0 / (1.f + __expf(-v0));
                    v1 = v1 / (1.f + __expf(-v1));
                }
                if (EPI == 1 || EPI == 3) {
                    v0 += R[row * ldr + c0];
                    v1 += R[row * ldr + c0 + 1];
                }
                float s0 = RC ? rtf(v0) : v0;
                float s1 = RC ? rtf(v1) : v1;
                float2 st = { s0, s1 };
                *(float2*)(C + row * ldc + c0) = st;
                if (DUAL) {
                    float2 st2 = { rtf(v0), rtf(v1) };
                    *(float2*)(C2 + row * ldc + c0) = st2;
                }
            }
        }
    }
}

template<int EPI, int RC, int DUAL>
__global__ __launch_bounds__(256, 2)
void tgemm_k(int M, int N, int K,
             const float* __restrict__ A, int lda, long long sA,
             const float* __restrict__ B, int ldb, long long sB,
             float* __restrict__ C, int ldc, long long sC,
             const float* __restrict__ R, int ldr, long long sR,
             float* __restrict__ C2) {
    extern __shared__ float smem[];
    int bz = blockIdx.z;
    A += (size_t)bz * sA; B += (size_t)bz * sB; C += (size_t)bz * sC;
    if (EPI == 1 || EPI == 3) R += (size_t)bz * sR;
    gemm_core<EPI, RC, DUAL>(K, A, lda, B, ldb, C, ldc, R, ldr, C2,
                             smem, blockIdx.y * 128, blockIdx.x * 128);
}

// batched QKV: one launch, grid.z selects (weight, output); V output rounded
__global__ __launch_bounds__(256, 2)
void qkv_k(const float* __restrict__ A,
           const float* __restrict__ B0, const float* __restrict__ B1,
           const float* __restrict__ B2,
           float* __restrict__ C0, float* __restrict__ C1, float* __restrict__ C2o) {
    extern __shared__ float smem[];
    int bz = blockIdx.z;
    const float* B = (bz == 0) ? B0 : (bz == 1) ? B1 : B2;
    float* C = (bz == 0) ? C0 : (bz == 1) ? C1 : C2o;
    if (bz == 2)
        gemm_core<0, 1, 0>(D_, A, D_, B, D_, C, D_, nullptr, 0, nullptr,
                           smem, blockIdx.y * 128, blockIdx.x * 128);
    else
        gemm_core<0, 0, 0>(D_, A, D_, B, D_, C, D_, nullptr, 0, nullptr,
                           smem, blockIdx.y * 128, blockIdx.x * 128);
}

// ---------------- RoPE (in-place, outputs tf32-rounded for MMA scores) ------
__global__ void rope_k(float* __restrict__ q, float* __restrict__ k) {
    int idx = blockIdx.x * 256 + threadIdx.x;
    int r = idx & 31;
    int h = (idx >> 5) & (NH - 1);
    int s = (idx >> 10) & (S_ - 1);
    int b = idx >> 20;
    float inv = powf(10000.f, -(float)(2 * r) / (float)HDIM);
    float ang = (float)s * inv;
    float sn, cs;
    sincosf(ang, &sn, &cs);
    size_t base = ((size_t)(b * S_ + s)) * D_ + h * HDIM;
    float q0 = q[base + r], q1 = q[base + r + 32];
    q[base + r]      = rtf(q0 * cs - q1 * sn);
    q[base + r + 32] = rtf(q1 * cs + q0 * sn);
    float k0 = k[base + r], k1 = k[base + r + 32];
    k[base + r]      = rtf(k0 * cs - k1 * sn);
    k[base + r + 32] = rtf(k1 * cs + k0 * sn);
}

// ---------------- scores via tf32 MMA: packed triangle, B via ldsm ----------
#define SC_LD 68
#define SC_SMEM (2 * 128 * SC_LD * 4)

__global__ __launch_bounds__(256)
void scores_mma_k(const float* __restrict__ q, const float* __restrict__ k,
                  float* __restrict__ attn) {
    int bh = blockIdx.y;
    int b = bh >> 5, h = bh & 31;
    int t = blockIdx.x;
    int ib = 0;
    while ((ib + 1) * (ib + 2) / 2 <= t) ib++;
    int jb = t - ib * (ib + 1) / 2;
    extern __shared__ float smem[];
    float* Qs = smem;
    float* Ks = smem + 128 * SC_LD;
    unsigned sQb = (unsigned)__cvta_generic_to_shared(Qs);
    unsigned sKb = (unsigned)__cvta_generic_to_shared(Ks);
    const float* qb = q + ((size_t)b * S_ + ib * 128) * D_ + h * HDIM;
    const float* kb = k + ((size_t)b * S_ + jb * 128) * D_ + h * HDIM;
    int tid = threadIdx.x;
#pragma unroll
    for (int i = 0; i < 8; i++) {
        int ch = tid + i * 256;
        int r = ch >> 4, c = (ch & 15) * 4;
        *(float4*)&Qs[r * SC_LD + c] = *(const float4*)(qb + (size_t)r * D_ + c);
        *(float4*)&Ks[r * SC_LD + c] = *(const float4*)(kb + (size_t)r * D_ + c);
    }
    __syncthreads();
    int lane = tid & 31, warp = tid >> 5;
    int wm = warp >> 2, wn = warp & 3;
    int lr = lane >> 2, lc = lane & 3;
    int lane15 = lane & 15, khalf = (lane >> 4) * 4;
    float acc[4][4][4];
#pragma unroll
    for (int mt = 0; mt < 4; mt++)
#pragma unroll
        for (int nt = 0; nt < 4; nt++)
#pragma unroll
            for (int i = 0; i < 4; i++) acc[mt][nt][i] = 0.f;
#pragma unroll
    for (int ks = 0; ks < 8; ks++) {
        int kk = ks * 8;
        unsigned af[4][4], bf[4][2], bq[2][4];
#pragma unroll
        for (int mt = 0; mt < 4; mt++) {
            int r = wm * 64 + mt * 16 + lane15;
            ldsm_x4(af[mt], sQb + (unsigned)(r * SC_LD + kk + khalf) * 4);
        }
#pragma unroll
        for (int ntp = 0; ntp < 2; ntp++) {
            int n = wn * 32 + ntp * 16 + lane15;
            ldsm_x4(bq[ntp], sKb + (unsigned)(n * SC_LD + kk + khalf) * 4);
        }
        bf[0][0] = bq[0][0]; bf[0][1] = bq[0][2];
        bf[1][0] = bq[0][1]; bf[1][1] = bq[0][3];
        bf[2][0] = bq[1][0]; bf[2][1] = bq[1][2];
        bf[3][0] = bq[1][1]; bf[3][1] = bq[1][3];
#pragma unroll
        for (int mt = 0; mt < 4; mt++)
#pragma unroll
            for (int nt = 0; nt < 4; nt++)
                mma_tf32(acc[mt][nt], af[mt], bf[nt]);
    }
    float* ob = attn + (size_t)bh * S_ * S_;
#pragma unroll
    for (int mt = 0; mt < 4; mt++) {
        int r0 = ib * 128 + wm * 64 + mt * 16 + lr;
#pragma unroll
        for (int nt = 0; nt < 4; nt++) {
            int c0 = jb * 128 + wn * 32 + nt * 8 + 2 * lc;
#pragma unroll
            for (int half = 0; half < 2; half++) {
                float2 st = { acc[mt][nt][half * 2 + 0] * 0.125f,
                              acc[mt][nt][half * 2 + 1] * 0.125f };
                *(float2*)(ob + (size_t)(r0 + half * 8) * S_ + c0) = st;
            }
        }
    }
}

// ---------------- causal softmax -------------------------------------------
__global__ __launch_bounds__(256)
void softmax_k(float* __restrict__ attn) {
    size_t row = blockIdx.x;
    int i = (int)(row & (S_ - 1));
    float* p = attn + row * S_;
    int len = i + 1;
    int blockend = ((i >> 7) + 1) << 7;
    int tid = threadIdx.x;
    __shared__ float sh[8];
    float x[4];
#pragma unroll
    for (int jt = 0; jt < 4; jt++) {
        int j = tid + jt * 256;
        x[jt] = (j < len) ? p[j] : -3.4e38f;
    }
    float m = fmaxf(fmaxf(x[0], x[1]), fmaxf(x[2], x[3]));
#pragma unroll
    for (int o = 16; o > 0; o >>= 1) m = fmaxf(m, __shfl_xor_sync(~0u, m, o));
    if ((tid & 31) == 0) sh[tid >> 5] = m;
    __syncthreads();
    m = sh[0];
#pragma unroll
    for (int z = 1; z < 8; z++) m = fmaxf(m, sh[z]);
    __syncthreads();
    float e[4], s = 0.f;
#pragma unroll
    for (int jt = 0; jt < 4; jt++) {
        int j = tid + jt * 256;
        e[jt] = (j < len) ? __expf(x[jt] - m) : 0.f;
        s += e[jt];
    }
#pragma unroll
    for (int o = 16; o > 0; o >>= 1) s += __shfl_xor_sync(~0u, s, o);
    if ((tid & 31) == 0) sh[tid >> 5] = s;
    __syncthreads();
    s = sh[0];
#pragma unroll
    for (int z = 1; z < 8; z++) s += sh[z];
    float inv = 1.f / s;
#pragma unroll
    for (int jt = 0; jt < 4; jt++) {
        int j = tid + jt * 256;
        if (j < blockend) p[j] = rtf(e[jt] * inv);
    }
}

// ---------------- attn @ V via tf32 MMA (causal K truncation) ---------------
__global__ __launch_bounds__(256)
void av_mma_k(const float* __restrict__ attn, const float* __restrict__ v,
              float* __restrict__ ao) {
    constexpr int ALD = 36, BLD = 72;
    __shared__ float As[2][128 * ALD];
    __shared__ float Bs[2][32 * BLD];
    unsigned sAb = (unsigned)__cvta_generic_to_shared(&As[0][0]);
    unsigned sBb = (unsigned)__cvta_generic_to_shared(&Bs[0][0]);
    int bh = blockIdx.y;
    int b = bh >> 5, h = bh & 31;
    int ib = blockIdx.x;
    const float* ab = attn + (size_t)bh * S_ * S_ + (size_t)ib * 128 * S_;
    const float* vb = v + (size_t)b * S_ * D_ + h * HDIM;
    int tid = threadIdx.x, lane = tid & 31, warp = tid >> 5;
    int wm = warp >> 1, wn = warp & 1;
    int lr = lane >> 2, lc = lane & 3;
    int lane15 = lane & 15, khalf = (lane >> 4) * 4;
    int ntile = (ib + 1) * 4;

    auto issue = [&](int kt, int st) {
#pragma unroll
        for (int i = 0; i < 4; i++) {
            int ch = tid + i * 256;
            int r = ch >> 3, c = ch & 7;
            cpa16(sAb + (unsigned)(st * 128 * ALD + r * ALD + c * 4) * 4,
                  ab + (size_t)r * S_ + kt * 32 + c * 4);
        }
#pragma unroll
        for (int i = 0; i < 2; i++) {
            int ch = tid + i * 256;
            int r = ch >> 4, c = ch & 15;
            cpa16(sBb + (unsigned)(st * 32 * BLD + r * BLD + c * 4) * 4,
                  vb + (size_t)(kt * 32 + r) * D_ + c * 4);
        }
    };

    float acc[2][4][4];
#pragma unroll
    for (int mt = 0; mt < 2; mt++)
#pragma unroll
        for (int nt = 0; nt < 4; nt++)
#pragma unroll
            for (int i = 0; i < 4; i++) acc[mt][nt][i] = 0.f;

    issue(0, 0);
    asm volatile("cp.async.commit_group;" ::: "memory");
    for (int it = 0; it < ntile; it++) {
        int cur = it & 1;
        if (it + 1 < ntile) {
            issue(it + 1, cur ^ 1);
            asm volatile("cp.async.commit_group;" ::: "memory");
            asm volatile("cp.async.wait_group 1;" ::: "memory");
        } else {
            asm volatile("cp.async.wait_group 0;" ::: "memory");
        }
        __syncthreads();
        unsigned aStage = sAb + (unsigned)(cur * 128 * ALD) * 4;
#pragma unroll
        for (int ks = 0; ks < 4; ks++) {
            int kk = ks * 8;
            unsigned af[2][4], bf[4][2];
#pragma unroll
            for (int mt = 0; mt < 2; mt++) {
                int r = wm * 32 + mt * 16 + lane15;
                ldsm_x4(af[mt], aStage + (unsigned)(r * ALD + kk + khalf) * 4);
            }
#pragma unroll
            for (int nt = 0; nt < 4; nt++) {
                int c = wn * 32 + nt * 8 + lr;
                const unsigned* p = (const unsigned*)&Bs[cur][(kk + lc) * BLD + c];
                bf[nt][0] = p[0];
                bf[nt][1] = p[4 * BLD];
            }
#pragma unroll
            for (int mt = 0; mt < 2; mt++)
#pragma unroll
                for (int nt = 0; nt < 4; nt++)
                    mma_tf32(acc[mt][nt], af[mt], bf[nt]);
        }
        __syncthreads();
    }
#pragma unroll
    for (int mt = 0; mt < 2; mt++) {
        int r0 = ib * 128 + wm * 32 + mt * 16 + lr;
#pragma unroll
        for (int nt = 0; nt < 4; nt++) {
            int c0 = wn * 32 + nt * 8 + 2 * lc;
#pragma unroll
            for (int half = 0; half < 2; half++) {
                size_t row = (size_t)(b * S_ + r0 + half * 8);
                float2 st = { rtf(acc[mt][nt][half * 2 + 0]),
                              rtf(acc[mt][nt][half * 2 + 1]) };
                *(float2*)(ao + row * D_ + h * HDIM + c0) = st;
            }
        }
    }
}

// ---------------- adjacency constant for masked pairs ------------------------
__global__ void c0_k(const float* __restrict__ b1, const float* __restrict__ W2,
                     const float* __restrict__ b2) {
    int t = threadIdx.x;
    float v = fmaxf(b1[t], 0.f) * W2[t];
#pragma unroll
    for (int o = 16; o > 0; o >>= 1) v += __shfl_xor_sync(~0u, v, o);
    __shared__ float sh[2];
    if ((t & 31) == 0) sh[t >> 5] = v;
    __syncthreads();
    if (t == 0) g_c0 = b2[0] + sh[0] + sh[1];
}

__global__ void adjfill_k(float* __restrict__ adj) {
    int i = blockIdx.x, b = blockIdx.y;
    int start = ((i >> 7) + 1) << 7;
    if (start >= S_) return;
    float val = rtf(1.f / (1.f + __expf(-g_c0)));
    float* p = adj + ((size_t)b * S_ + i) * S_;
    for (int j = start + threadIdx.x; j < S_; j += 128) p[j] = val;
}

// ---------------- adjacency MLP via tf32 MMA (lower tiles only) -------------
__global__ __launch_bounds__(256)
void adj_mma_k(const float* __restrict__ attn,
               const float* __restrict__ W1, const float* __restrict__ b1,
               const float* __restrict__ W2, const float* __restrict__ b2,
               float* __restrict__ adj) {
    constexpr int ALD = 36, WLD = 72;
    int jt = blockIdx.x, i = blockIdx.y, b = blockIdx.z;
    if (jt > (i >> 7)) return;
    __shared__ float As[128 * ALD];
    __shared__ float Ws[32 * WLD];
    __shared__ float sb1[AH_], sw2[AH_];
    int tid = threadIdx.x;
#pragma unroll
    for (int it = 0; it < 8; it++) {
        int idx = tid + it * 256;
        Ws[(idx >> 6) * WLD + (idx & 63)] = rtf(W1[idx]);
    }
    if (tid < AH_) { sb1[tid] = b1[tid]; sw2[tid] = W2[tid]; }
#pragma unroll
    for (int it = 0; it < 4; it++) {
        int ch = tid + it * 256;
        int h = ch >> 5, jq = ch & 31;
        float4 a4 = *(const float4*)(attn +
            (((size_t)(b * NH + h) * S_ + i) * S_) + jt * 128 + jq * 4);
        As[(jq * 4 + 0) * ALD + h] = a4.x;
        As[(jq * 4 + 1) * ALD + h] = a4.y;
        As[(jq * 4 + 2) * ALD + h] = a4.z;
        As[(jq * 4 + 3) * ALD + h] = a4.w;
    }
    __syncthreads();
    int lane = tid & 31, warp = tid >> 5;
    int lr = lane >> 2, lc = lane & 3;
    float acc[8][4];
#pragma unroll
    for (int nt = 0; nt < 8; nt++)
#pragma unroll
        for (int z = 0; z < 4; z++) acc[nt][z] = 0.f;
#pragma unroll
    for (int ks = 0; ks < 4; ks++) {
        int kk = ks * 8;
        unsigned af[4];
        int r = warp * 16 + lr;
        const unsigned* p = (const unsigned*)&As[r * ALD + kk + lc];
        af[0] = p[0];
        af[1] = p[8 * ALD];
        af[2] = p[4];
        af[3] = p[8 * ALD + 4];
#pragma unroll
        for (int nt = 0; nt < 8; nt++) {
            int c = nt * 8 + lr;
            const unsigned* q = (const unsigned*)&Ws[(kk + lc) * WLD + c];
            unsigned bf[2] = { q[0], q[4 * WLD] };
            mma_tf32(acc[nt], af, bf);
        }
    }
    float s0 = 0.f, s1 = 0.f;
#pragma unroll
    for (int nt = 0; nt < 8; nt++) {
        int c0 = nt * 8 + 2 * lc, c1 = c0 + 1;
        s0 += fmaxf(acc[nt][0] + sb1[c0], 0.f) * sw2[c0]
            + fmaxf(acc[nt][1] + sb1[c1], 0.f) * sw2[c1];
        s1 += fmaxf(acc[nt][2] + sb1[c0], 0.f) * sw2[c0]
            + fmaxf(acc[nt][3] + sb1[c1], 0.f) * sw2[c1];
    }
    s0 += __shfl_xor_sync(~0u, s0, 1); s0 += __shfl_xor_sync(~0u, s0, 2);
    s1 += __shfl_xor_sync(~0u, s1, 1); s1 += __shfl_xor_sync(~0u, s1, 2);
    if (lc == 0) {
        float bb = b2[0];
        int j0 = jt * 128 + warp * 16;
        size_t base = ((size_t)b * S_ + i) * S_;
        adj[base + j0 + lr]     = rtf(1.f / (1.f + __expf(-(s0 + bb))));
        adj[base + j0 + lr + 8] = rtf(1.f / (1.f + __expf(-(s1 + bb))));
    }
}

// ---------------- launch ----------------------------------------------------
extern "C" void kernel_launch(void* const* d_in, const int* in_sizes, int n_in,
                              void* d_out, int out_size) {
    const float* x        = (const float*)d_in[0];
    const float* w_q      = (const float*)d_in[1];
    const float* w_k      = (const float*)d_in[2];
    const float* w_v      = (const float*)d_in[3];
    const float* w_o      = (const float*)d_in[4];
    const float* norm1_w  = (const float*)d_in[5];
    const float* norm2_w  = (const float*)d_in[6];
    const float* w_adj1   = (const float*)d_in[7];
    const float* b_adj1   = (const float*)d_in[8];
    const float* w_adj2   = (const float*)d_in[9];
    const float* b_adj2   = (const float*)d_in[10];
    const float* w_gnn    = (const float*)d_in[11];
    const float* w_mlp_in = (const float*)d_in[12];
    const float* w_mlp_out= (const float*)d_in[13];

    float *h, *q, *k, *v, *attn, *ao, *h1, *h1t, *adj, *msg, *h2, *h3, *t;
    float *wq, *wk, *wv, *wo, *wg, *wi, *wo2;
    cudaGetSymbolAddress((void**)&h,    g_h);
    cudaGetSymbolAddress((void**)&q,    g_q);
    cudaGetSymbolAddress((void**)&k,    g_k);
    cudaGetSymbolAddress((void**)&v,    g_v);
    cudaGetSymbolAddress((void**)&attn, g_attn);
    cudaGetSymbolAddress((void**)&ao,   g_ao);
    cudaGetSymbolAddress((void**)&h1,   g_h1);
    cudaGetSymbolAddress((void**)&h1t,  g_h1t);
    cudaGetSymbolAddress((void**)&adj,  g_adj);
    cudaGetSymbolAddress((void**)&msg,  g_msg);
    cudaGetSymbolAddress((void**)&h2,   g_h2);
    cudaGetSymbolAddress((void**)&h3,   g_h3);
    cudaGetSymbolAddress((void**)&t,    g_t);
    cudaGetSymbolAddress((void**)&wq,   g_wq);
    cudaGetSymbolAddress((void**)&wk,   g_wk);
    cudaGetSymbolAddress((void**)&wv,   g_wv);
    cudaGetSymbolAddress((void**)&wo,   g_wo);
    cudaGetSymbolAddress((void**)&wg,   g_wg);
    cudaGetSymbolAddress((void**)&wi,   g_wi);
    cudaGetSymbolAddress((void**)&wo2,  g_wo2);

    cudaFuncSetAttribute(qkv_k,          cudaFuncAttributeMaxDynamicSharedMemorySize, TG_SMEM);
    cudaFuncSetAttribute(tgemm_k<0,1,0>, cudaFuncAttributeMaxDynamicSharedMemorySize, TG_SMEM);
    cudaFuncSetAttribute(tgemm_k<1,0,1>, cudaFuncAttributeMaxDynamicSharedMemorySize, TG_SMEM);
    cudaFuncSetAttribute(tgemm_k<3,0,0>, cudaFuncAttributeMaxDynamicSharedMemorySize, TG_SMEM);
    cudaFuncSetAttribute(tgemm_k<2,1,0>, cudaFuncAttributeMaxDynamicSharedMemorySize, TG_SMEM);
    cudaFuncSetAttribute(tgemm_k<1,0,0>, cudaFuncAttributeMaxDynamicSharedMemorySize, TG_SMEM);
    cudaFuncSetAttribute(scores_mma_k,   cudaFuncAttributeMaxDynamicSharedMemorySize, SC_SMEM);

    // pre-round ALL weights to tf32 in one launch (rna: zero-mean rounding)
    cvtw_all_k<<<53248, 256>>>(w_q, wq, w_k, wk, w_v, wv, w_o, wo,
                               w_gnn, wg, w_mlp_in, wi, w_mlp_out, wo2);

    // adjacency constant (for fully-masked pairs)
    c0_k<<<1, 64>>>(b_adj1, w_adj2, b_adj2);

    // h = rmsnorm(x, norm1)  (tf32-rounded)
    rmsnorm_k<<<BS_, 256>>>(x, norm1_w, h);

    // q/k/v = h @ W   (one batched launch; v rounded)
    qkv_k<<<dim3(16, 16, 3), 256, TG_SMEM>>>(h, wq, wk, wv, q, k, v);

    // RoPE in place (rounded)
    rope_k<<<(B_ * S_ * NH * 32) / 256, 256>>>(q, k);

    // scores (MMA, packed lower-triangle grid, B via ldsm) + causal softmax
    scores_mma_k<<<dim3(36, B_ * NH), 256, SC_SMEM>>>(q, k, attn);
    softmax_k<<<B_ * NH * S_, 256>>>(attn);

    // attn @ V  (MMA, ao rounded)
    av_mma_k<<<dim3(8, B_ * NH), 256>>>(attn, v, ao);

    // h1 = x + ao @ w_o   (exact h1 + rounded h1t)
    tgemm_k<1,0,1><<<dim3(16, 16), 256, TG_SMEM>>>(BS_, D_, D_, ao, D_, 0, wo, D_, 0, h1, D_, 0, x, D_, 0, h1t);

    // adjacency: constant fill for masked region + MMA on lower tiles
    adjfill_k<<<dim3(S_, B_), 128>>>(adj);
    adj_mma_k<<<dim3(8, S_, B_), 256>>>(attn, w_adj1, b_adj1, w_adj2, b_adj2, adj);

    // msg = adj @ h1t
    tgemm_k<0,1,0><<<dim3(16, 8, B_), 256, TG_SMEM>>>(S_, D_, S_,
        adj, S_, (long long)S_ * S_,
        h1t, D_, (long long)S_ * D_,
        msg, D_, (long long)S_ * D_, nullptr, 0, 0, nullptr);

    // h2 = h1 + silu(msg @ w_gnn)
    tgemm_k<3,0,0><<<dim3(16, 16), 256, TG_SMEM>>>(BS_, D_, D_, msg, D_, 0, wg, D_, 0, h2, D_, 0, h1, D_, 0, nullptr);

    // h3 = rmsnorm(h2, norm2)  (rounded)
    rmsnorm_k<<<BS_, 256>>>(h2, norm2_w, h3);

    // t = silu(h3 @ w_mlp_in)  (rounded: feeds mlp_out GEMM)
    tgemm_k<2,1,0><<<dim3(64, 16), 256, TG_SMEM>>>(BS_, ID_, D_, h3, D_, 0, wi, ID_, 0, t, ID_, 0, nullptr, 0, 0, nullptr);

    // out = h2 + t @ w_mlp_out
    tgemm_k<1,0,0><<<dim3(16, 16), 256, TG_SMEM>>>(BS_, D_, ID_, t, ID_, 0, wo2, D_, 0,
                                                   (float*)d_out, D_, 0, h2, D_, 0, nullptr);
}